// round 1
// baseline (speedup 1.0000x reference)
#include <cuda_runtime.h>
#include <cuda_bf16.h>
#include <math_constants.h>

// Collapsed model:
//   out[b,n,e] = cd[b,n]*u[e] + density[b,n]*v[e] + c[e]
// u/v/c precomputed from the tiny weight tensors.

__device__ float g_u[128];
__device__ float g_v[128];
__device__ float g_c[128];

#define D3 42
#define NPT 49
#define EOUT 128

__global__ void precompute_uvc(const float* __restrict__ W_dist,
                               const float* __restrict__ b_dist,
                               const float* __restrict__ emb,
                               const float* __restrict__ W_den,
                               const float* __restrict__ b_den,
                               const float* __restrict__ W_out,
                               const float* __restrict__ b_out) {
    int e = threadIdx.x;  // 0..127
    float u = 0.f, v = 0.f, c = 0.f;
#pragma unroll 7
    for (int d = 0; d < D3; d++) {
        float wo0 = W_out[d * EOUT + e];            // dist block
        float wo1 = W_out[(D3 + d) * EOUT + e];     // count block
        float wo2 = W_out[(2 * D3 + d) * EOUT + e]; // density block
        u += W_dist[d] * wo0;
        v += W_den[d] * wo2;
        c += b_dist[d] * wo0 + emb[NPT * D3 + d] * wo1 + b_den[d] * wo2;
    }
    g_u[e] = u;
    g_v[e] = v;
    g_c[e] = c + b_out[e];
}

__global__ __launch_bounds__(256, 8)
void nrpf_kernel(const float* __restrict__ points, float* __restrict__ out) {
    const int b = blockIdx.x;
    const int t = threadIdx.x;

    __shared__ float sp[NPT * 3];     // 147 floats, this batch's points
    __shared__ float s_cent[3];
    __shared__ float s_cd[NPT];
    __shared__ float s_dn[NPT];
    __shared__ float4 s_u[32], s_v[32], s_c[32];

    // load points (147 floats) with first 147 threads
    if (t < NPT * 3) sp[t] = points[(size_t)b * (NPT * 3) + t];
    // load u/v/c vectors as float4 with a disjoint warp
    if (t >= 160 && t < 192) {
        int j = t - 160;
        s_u[j] = reinterpret_cast<const float4*>(g_u)[j];
        s_v[j] = reinterpret_cast<const float4*>(g_v)[j];
        s_c[j] = reinterpret_cast<const float4*>(g_c)[j];
    }
    __syncthreads();

    // centroid: 3 threads, each sums one dim over 49 points
    if (t < 3) {
        float s = 0.f;
#pragma unroll 7
        for (int n = 0; n < NPT; n++) s += sp[n * 3 + t];
        s_cent[t] = s * (1.0f / 49.0f);
    }
    __syncthreads();

    // per-point: centroid distance + 3-NN mean distance
    if (t < NPT) {
        float px = sp[t * 3 + 0], py = sp[t * 3 + 1], pz = sp[t * 3 + 2];
        float dx = px - s_cent[0], dy = py - s_cent[1], dz = pz - s_cent[2];
        s_cd[t] = sqrtf(dx * dx + dy * dy + dz * dz);

        float m0 = CUDART_INF_F, m1 = CUDART_INF_F, m2 = CUDART_INF_F;
#pragma unroll 7
        for (int m = 0; m < NPT; m++) {
            float ax = px - sp[m * 3 + 0];
            float ay = py - sp[m * 3 + 1];
            float az = pz - sp[m * 3 + 2];
            float d2 = ax * ax + ay * ay + az * az;
            if (m == t) d2 = CUDART_INF_F;  // mask self
            if (d2 < m0)      { m2 = m1; m1 = m0; m0 = d2; }
            else if (d2 < m1) { m2 = m1; m1 = d2; }
            else if (d2 < m2) { m2 = d2; }
        }
        s_dn[t] = (sqrtf(m0) + sqrtf(m1) + sqrtf(m2)) * (1.0f / 3.0f);
    }
    __syncthreads();

    // epilogue: out[b,n,e] = cd[n]*u[e] + dn[n]*v[e] + c[e]
    // 49*128 = 6272 floats = 1568 float4s, coalesced STG.128
    float4* outp = reinterpret_cast<float4*>(out + (size_t)b * (NPT * EOUT));
#pragma unroll
    for (int j = t; j < NPT * 32; j += 256) {
        int n = j >> 5;        // point index
        int q = j & 31;        // float4 index within the 128-wide row
        float cd = s_cd[n], dn = s_dn[n];
        float4 u = s_u[q], v = s_v[q], c = s_c[q];
        float4 r;
        r.x = fmaf(cd, u.x, fmaf(dn, v.x, c.x));
        r.y = fmaf(cd, u.y, fmaf(dn, v.y, c.y));
        r.z = fmaf(cd, u.z, fmaf(dn, v.z, c.z));
        r.w = fmaf(cd, u.w, fmaf(dn, v.w, c.w));
        outp[j] = r;
    }
}

extern "C" void kernel_launch(void* const* d_in, const int* in_sizes, int n_in,
                              void* d_out, int out_size) {
    const float* points = (const float*)d_in[0];
    const float* W_dist = (const float*)d_in[1];
    const float* b_dist = (const float*)d_in[2];
    const float* emb    = (const float*)d_in[3];
    const float* W_den  = (const float*)d_in[4];
    const float* b_den  = (const float*)d_in[5];
    const float* W_out  = (const float*)d_in[6];
    const float* b_out  = (const float*)d_in[7];
    float* out = (float*)d_out;

    int B = in_sizes[0] / (NPT * 3);

    precompute_uvc<<<1, 128>>>(W_dist, b_dist, emb, W_den, b_den, W_out, b_out);
    nrpf_kernel<<<B, 256>>>(points, out);
}

// round 2
// speedup vs baseline: 1.6445x; 1.6445x over previous
#include <cuda_runtime.h>
#include <cuda_bf16.h>
#include <math_constants.h>

// Collapsed model:
//   out[b,n,e] = cd[b,n]*u[e] + density[b,n]*v[e] + c[e]
// u/v/c precomputed from the tiny weight tensors.

__device__ float g_u[128];
__device__ float g_v[128];
__device__ float g_c[128];

#define D3   42
#define NPT  49
#define EOUT 128
#define BPB  4                  // batches per block
#define ROWS (BPB * NPT)        // 196 rows of 128 floats per block

// ---------------------------------------------------------------------------
// Parallel precompute: 1024 threads, e = t&127, K-slice s = t>>7 (8 slices).
// Each slice covers d = s, s+8, ... < 42; smem tree-reduce over slices.
// ---------------------------------------------------------------------------
__global__ __launch_bounds__(1024)
void precompute_uvc(const float* __restrict__ W_dist,
                    const float* __restrict__ b_dist,
                    const float* __restrict__ emb,
                    const float* __restrict__ W_den,
                    const float* __restrict__ b_den,
                    const float* __restrict__ W_out,
                    const float* __restrict__ b_out) {
    __shared__ float su[8][128], sv[8][128], sc[8][128];
    int t = threadIdx.x;
    int e = t & 127;
    int s = t >> 7;          // 0..7
    float u = 0.f, v = 0.f, c = 0.f;
    for (int d = s; d < D3; d += 8) {
        float wo0 = W_out[d * EOUT + e];            // dist block
        float wo1 = W_out[(D3 + d) * EOUT + e];     // count block
        float wo2 = W_out[(2 * D3 + d) * EOUT + e]; // density block
        u += W_dist[d] * wo0;
        v += W_den[d] * wo2;
        c += b_dist[d] * wo0 + emb[NPT * D3 + d] * wo1 + b_den[d] * wo2;
    }
    su[s][e] = u; sv[s][e] = v; sc[s][e] = c;
    __syncthreads();
    if (s == 0) {
        float U = 0.f, V = 0.f, C = 0.f;
#pragma unroll
        for (int k = 0; k < 8; k++) { U += su[k][e]; V += sv[k][e]; C += sc[k][e]; }
        g_u[e] = U;
        g_v[e] = V;
        g_c[e] = C + b_out[e];
    }
}

// ---------------------------------------------------------------------------
// Main kernel: 4 batches per block, 256 threads.
// ---------------------------------------------------------------------------
__global__ __launch_bounds__(256, 8)
void nrpf_kernel(const float* __restrict__ points, float* __restrict__ out,
                 int nrows_total) {
    const int t = threadIdx.x;
    const int g = t >> 6;       // batch slot 0..3
    const int lt = t & 63;      // lane within slot

    __shared__ float sp[BPB * NPT * 3];   // 588 floats
    __shared__ float s_cent[BPB * 3];
    __shared__ float s_cd[ROWS];
    __shared__ float s_dn[ROWS];

    // u/v/c register-resident: thread owns float4 column q = t & 31
    const int q = t & 31;
    float4 ru = reinterpret_cast<const float4*>(g_u)[q];
    float4 rv = reinterpret_cast<const float4*>(g_v)[q];
    float4 rc = reinterpret_cast<const float4*>(g_c)[q];

    // load 4 batches of points: 588 contiguous floats
    const size_t pbase = (size_t)blockIdx.x * (BPB * NPT * 3);
#pragma unroll
    for (int j = t; j < BPB * NPT * 3; j += 256)
        sp[j] = points[pbase + j];
    __syncthreads();

    // centroids: 12 threads
    if (t < BPB * 3) {
        int gg = t / 3, dim = t % 3;
        const float* p = sp + gg * (NPT * 3);
        float ssum = 0.f;
#pragma unroll 7
        for (int n = 0; n < NPT; n++) ssum += p[n * 3 + dim];
        s_cent[t] = ssum * (1.0f / 49.0f);
    }
    __syncthreads();

    // per-point centroid distance + 3-NN mean (196 of 256 threads active)
    if (lt < NPT) {
        const float* p = sp + g * (NPT * 3);
        float px = p[lt * 3 + 0], py = p[lt * 3 + 1], pz = p[lt * 3 + 2];
        float dx = px - s_cent[g * 3 + 0];
        float dy = py - s_cent[g * 3 + 1];
        float dz = pz - s_cent[g * 3 + 2];
        s_cd[g * NPT + lt] = sqrtf(dx * dx + dy * dy + dz * dz);

        float m0 = CUDART_INF_F, m1 = CUDART_INF_F, m2 = CUDART_INF_F;
#pragma unroll 7
        for (int m = 0; m < NPT; m++) {
            float ax = px - p[m * 3 + 0];
            float ay = py - p[m * 3 + 1];
            float az = pz - p[m * 3 + 2];
            float d2 = ax * ax + ay * ay + az * az;
            if (m == lt) d2 = CUDART_INF_F;   // mask self
            if (d2 < m0)      { m2 = m1; m1 = m0; m0 = d2; }
            else if (d2 < m1) { m2 = m1; m1 = d2; }
            else if (d2 < m2) { m2 = d2; }
        }
        s_dn[g * NPT + lt] = (sqrtf(m0) + sqrtf(m1) + sqrtf(m2)) * (1.0f / 3.0f);
    }
    __syncthreads();

    // epilogue: warp w handles rows w, w+8, ...; thread stores column q.
    // global row = blockIdx.x*196 + r  → address needs no division.
    const int w = t >> 5;
    const int row0 = blockIdx.x * ROWS;
    float4* outp = reinterpret_cast<float4*>(out) + (size_t)row0 * 32 + q;
#pragma unroll
    for (int r = w; r < ROWS; r += 8) {
        if (row0 + r >= nrows_total) break;
        float cd = s_cd[r], dn = s_dn[r];
        float4 o;
        o.x = fmaf(cd, ru.x, fmaf(dn, rv.x, rc.x));
        o.y = fmaf(cd, ru.y, fmaf(dn, rv.y, rc.y));
        o.z = fmaf(cd, ru.z, fmaf(dn, rv.z, rc.z));
        o.w = fmaf(cd, ru.w, fmaf(dn, rv.w, rc.w));
        outp[(size_t)r * 32] = o;
    }
}

extern "C" void kernel_launch(void* const* d_in, const int* in_sizes, int n_in,
                              void* d_out, int out_size) {
    const float* points = (const float*)d_in[0];
    const float* W_dist = (const float*)d_in[1];
    const float* b_dist = (const float*)d_in[2];
    const float* emb    = (const float*)d_in[3];
    const float* W_den  = (const float*)d_in[4];
    const float* b_den  = (const float*)d_in[5];
    const float* W_out  = (const float*)d_in[6];
    const float* b_out  = (const float*)d_in[7];
    float* out = (float*)d_out;

    int B = in_sizes[0] / (NPT * 3);
    int grid = (B + BPB - 1) / BPB;

    precompute_uvc<<<1, 1024>>>(W_dist, b_dist, emb, W_den, b_den, W_out, b_out);
    nrpf_kernel<<<grid, 256>>>(points, out, B * NPT);
}